// round 10
// baseline (speedup 1.0000x reference)
#include <cuda_runtime.h>
#include <cuda_fp16.h>
#include <cuda_bf16.h>
#include <cstdint>

// IntEinsum: out[b,t,f] = sum_d x[b,t,d] * (W_int4[d,f] / scale[f])
// GEMM M=1024, K=4096, N=16384, fp32 in/out.
// Round 10: k8-granularity MMA (m16n8k8) with ping-pong fragment
// double-buffering at ZERO extra register cost (12 live frag regs per k8
// step, 2 buffers = 24 = same as one k16 set). LDSM latency hidden under
// the previous step's MMA burst. Pipeline/staging/epilogue frozen from R9.

#define M_DIM 1024
#define N_DIM 16384
#define K_DIM 4096
#define W_ELEMS (K_DIM * N_DIM)

#define BK 64
#define NCHUNK (K_DIM / BK)          // 64
#define NSTAGE 3

#define RS 72                        // smem row stride (fp16), 144B rows
#define PLANE_BYTES (128 * RS * 2)   // 18432
#define STAGE_BYTES (2 * PLANE_BYTES)// 36864: A | B_t
#define BAR_OFF     (NSTAGE * STAGE_BYTES)      // 110592
#define SMEM_TOTAL  (BAR_OFF + 64)

// ---------------- device scratch ----------------
__device__ __half g_wT[(size_t)N_DIM * K_DIM];   // weights fp16, [n][k]
__device__ __half g_a[M_DIM * K_DIM];            // activations fp16
__device__ int g_fmt;

#define FMT_I8      0
#define FMT_I32     1
#define FMT_F32     2
#define FMT_BF16    3
#define FMT_PACKED2 4
#define FMT_PACKED8 5

__device__ __forceinline__ uint32_t smem_u32(const void* p) {
    uint32_t a;
    asm("{ .reg .u64 t; cvta.to.shared.u64 t, %1; cvt.u32.u64 %0, t; }"
        : "=r"(a) : "l"(p));
    return a;
}

// ---------------- format probe (warp-parallel, proven) ----------------
__global__ void probe_kernel(const uint32_t* __restrict__ W, int hint) {
    if (hint >= 0) { if (threadIdx.x == 0) g_fmt = hint; return; }
    const int lane = threadIdx.x;
    uint32_t w0 = W[lane * 2];
    uint32_t w1 = W[lane * 2 + 1];

    bool okf = true;
#pragma unroll
    for (int j = 0; j < 2; j++) {
        float f = __uint_as_float(j ? w1 : w0);
        if (!(f >= -8.f && f <= 7.f) || f != rintf(f)) okf = false;
    }
    if (__all_sync(0xFFFFFFFFu, okf)) { if (lane == 0) g_fmt = FMT_F32; return; }

    bool okb = true;
#pragma unroll
    for (int j = 0; j < 4; j++) {
        uint16_t u = (uint16_t)((j < 2 ? w0 : w1) >> (16 * (j & 1)));
        __nv_bfloat16 b = *reinterpret_cast<__nv_bfloat16*>(&u);
        float f = __bfloat162float(b);
        if (!(f >= -8.f && f <= 7.f) || f != rintf(f)) okb = false;
    }
    if (__all_sync(0xFFFFFFFFu, okb)) { if (lane == 0) g_fmt = FMT_BF16; return; }

    bool oki = ((((int)w0) >> 4) == 0 || (((int)w0) >> 4) == -1) &&
               ((((int)w1) >> 4) == 0 || (((int)w1) >> 4) == -1);
    if (lane == 0) g_fmt = __all_sync(0xFFFFFFFFu, oki) ? FMT_I32 : FMT_I8;
}

__device__ __forceinline__ int sx_nib(uint32_t w, int shift) {
    return ((int)(w << (28 - shift))) >> 28;
}

__device__ __forceinline__ int decode_w(const void* Wv, int fmt, size_t idx) {
    if (fmt == FMT_F32)  return (int)((const float*)Wv)[idx];
    if (fmt == FMT_BF16) return (int)__bfloat162float(((const __nv_bfloat16*)Wv)[idx]);
    if (fmt == FMT_I32)  return sx_nib(((const uint32_t*)Wv)[idx], 0);
    if (fmt == FMT_I8)   return sx_nib((uint32_t)((const uint8_t*)Wv)[idx], 0);
    if (fmt == FMT_PACKED2) {
        uint32_t b = ((const uint8_t*)Wv)[idx >> 1];
        return sx_nib(b, (int)(idx & 1) * 4);
    }
    uint32_t w = ((const uint32_t*)Wv)[idx >> 3];
    return sx_nib(w, (int)(idx & 7) * 4);
}

// ---------------- W convert + transpose: [k][n] fmt -> [n][k] fp16 ----------------
__global__ void convert_transpose_kernel(const void* __restrict__ Wv) {
    __shared__ __half tile[64 * RS];
    const int fmt = g_fmt;
    const int k0 = blockIdx.x * 64;
    const int n0 = blockIdx.y * 64;
    const int tid = threadIdx.x;

#pragma unroll
    for (int it = 0; it < 16; it++) {
        int idx = tid + it * 256;
        int r = idx >> 6;                      // k-local
        int c = idx & 63;                      // n-local (coalesced reads)
        int e = decode_w(Wv, fmt, (size_t)(k0 + r) * N_DIM + (n0 + c));
        tile[c * RS + r] = __float2half((float)e);
    }
    __syncthreads();
#pragma unroll
    for (int it = 0; it < 2; it++) {
        int q = tid + it * 256;
        int n = q >> 3;
        int cg = q & 7;
        uint4 v = *reinterpret_cast<const uint4*>(&tile[n * RS + cg * 8]);
        *reinterpret_cast<uint4*>(&g_wT[(size_t)(n0 + n) * K_DIM + k0 + cg * 8]) = v;
    }
}

// ---------------- A fp32 -> fp16 ----------------
__global__ void a_convert_kernel(const float* __restrict__ A) {
    size_t i = ((size_t)blockIdx.x * blockDim.x + threadIdx.x) * 4;
    float4 v = *reinterpret_cast<const float4*>(&A[i]);
    __half2 h0 = __floats2half2_rn(v.x, v.y);
    __half2 h1 = __floats2half2_rn(v.z, v.w);
    *reinterpret_cast<uint2*>(&g_a[i]) =
        make_uint2(*(uint32_t*)&h0, *(uint32_t*)&h1);
}

// ---------------- MMA / ldmatrix / mbarrier helpers ----------------
__device__ __forceinline__ void mma_f16_k8(float c[4], uint32_t a0, uint32_t a1,
                                           uint32_t b0) {
    asm volatile(
        "mma.sync.aligned.m16n8k8.row.col.f32.f16.f16.f32 "
        "{%0,%1,%2,%3}, {%4,%5}, {%6}, {%0,%1,%2,%3};\n"
        : "+f"(c[0]), "+f"(c[1]), "+f"(c[2]), "+f"(c[3])
        : "r"(a0), "r"(a1), "r"(b0));
}

#define LDMATRIX_X4(r0, r1, r2, r3, addr) \
    asm volatile("ldmatrix.sync.aligned.m8n8.x4.shared.b16 {%0,%1,%2,%3}, [%4];" \
        : "=r"(r0), "=r"(r1), "=r"(r2), "=r"(r3) : "r"(addr))

#define CP_ASYNC16(dst, src) \
    asm volatile("cp.async.cg.shared.global [%0], [%1], 16;" \
                 :: "r"(dst), "l"(src) : "memory")
#define CP_MBAR_ARRIVE(addr) \
    asm volatile("cp.async.mbarrier.arrive.noinc.shared.b64 [%0];" \
                 :: "r"(addr) : "memory")

#define MBARRIER_INIT(addr, cnt) \
    asm volatile("mbarrier.init.shared.b64 [%0], %1;" :: "r"(addr), "r"(cnt) : "memory")
#define MBARRIER_ARRIVE(addr) \
    asm volatile("mbarrier.arrive.shared.b64 _, [%0];" :: "r"(addr) : "memory")
#define MBARRIER_WAIT_PARITY(addr, ph) do {                                         \
    uint32_t _m = (addr); uint32_t _p = (ph); uint32_t _d;                          \
    asm volatile("{\n\t.reg .pred p;\n\t"                                           \
        "mbarrier.try_wait.parity.acquire.cta.shared::cta.b64 p, [%1], %2;\n\t"     \
        "selp.b32 %0, 1, 0, p;\n\t}" : "=r"(_d) : "r"(_m), "r"(_p) : "memory");     \
    if (!_d) {                                                                      \
        asm volatile("{\n\t.reg .pred P1;\n\t"                                      \
            "W%=:\n\t"                                                              \
            "mbarrier.try_wait.parity.acquire.cta.shared::cta.b64 P1, [%0], %1, 0x989680;\n\t" \
            "@P1 bra.uni D%=;\n\t"                                                  \
            "bra.uni W%=;\n\t"                                                      \
            "D%=:\n\t}" :: "r"(_m), "r"(_p) : "memory");                            \
    }                                                                               \
} while (0)

// ---------------- GEMM ----------------
__global__ __launch_bounds__(256, 2)
void int4_gemm_kernel(const float* __restrict__ S, float* __restrict__ C) {
    extern __shared__ __align__(128) char smem[];
    const uint32_t smb = smem_u32(smem);

    const int tid    = threadIdx.x;
    const int lane   = tid & 31;
    const int wid    = tid >> 5;
    const int warp_m = wid >> 1;     // 0..3 -> 32 rows
    const int warp_n = wid & 1;      // 0..1 -> 64 cols

    const int bm = blockIdx.x * 128;   // bm-fastest raster (B DRAM once)
    const int bn = blockIdx.y * 128;

    const uint32_t barb = smb + BAR_OFF;
    if (tid == 0) {
#pragma unroll
        for (int s = 0; s < NSTAGE; s++) {
            MBARRIER_INIT(barb + s * 16,     256);  // full
            MBARRIER_INIT(barb + s * 16 + 8, 8);    // empty
        }
    }
    __syncthreads();

    float c[2][8][4];
#pragma unroll
    for (int i = 0; i < 2; i++)
#pragma unroll
        for (int j = 0; j < 8; j++)
#pragma unroll
            for (int q = 0; q < 4; q++) c[i][j][q] = 0.f;

    // k8 ldmatrix lane offsets (bytes within a stage buffer):
    // A x4: mats m0-7|m8-15|m16-23|m24-31 at one k8 column -> row = wm*32+lane
    const uint32_t aOff = (uint32_t)((warp_m * 32 + lane) * RS * 2);
    // B x4: mats n0-7..n24-31 -> row = wn*64+lane; second x4 at +32 rows
    const uint32_t bOff = (uint32_t)((warp_n * 64 + lane) * RS * 2);

    auto issue_stage = [&](int chunk) {
        const uint32_t sb = smb + (uint32_t)(chunk % NSTAGE) * STAGE_BYTES;
        const int k0 = chunk * BK;
#pragma unroll
        for (int j = 0; j < 8; j++) {
            const int buf = j >> 2;                 // 0 = A, 1 = B_t
            const int q   = (tid + j * 256) & 1023;
            const int r   = q >> 3;
            const int cg  = q & 7;
            const __half* src = (buf == 0)
                ? &g_a [(size_t)(bm + r) * K_DIM + k0 + cg * 8]
                : &g_wT[(size_t)(bn + r) * K_DIM + k0 + cg * 8];
            CP_ASYNC16(sb + buf * PLANE_BYTES + r * (RS * 2) + cg * 16, src);
        }
    };

    // prologue: stage chunks 0..2 into virgin buffers
#pragma unroll
    for (int p = 0; p < NSTAGE; p++) {
        issue_stage(p);
        CP_MBAR_ARRIVE(barb + p * 16);
    }

    uint32_t fa[2][4];   // [buf][mt*2 + {a0,a1}]
    uint32_t fb[2][8];   // [buf][nt]

    int s = 0, fp = 0;
    for (int i = 0; i < NCHUNK; i++) {
        const uint32_t fullb  = barb + s * 16;
        const uint32_t emptyb = fullb + 8;

        MBARRIER_WAIT_PARITY(fullb, fp);

        const uint32_t sb    = smb + (uint32_t)s * STAGE_BYTES;
        const uint32_t aBase = sb + aOff;
        const uint32_t bBase = sb + PLANE_BYTES + bOff;

        // ping-pong over 8 k8 steps: load j+1's fragments, then MMA j's
        LDMATRIX_X4(fa[0][0], fa[0][1], fa[0][2], fa[0][3], aBase);
        LDMATRIX_X4(fb[0][0], fb[0][1], fb[0][2], fb[0][3], bBase);
        LDMATRIX_X4(fb[0][4], fb[0][5], fb[0][6], fb[0][7],
                    bBase + 32 * RS * 2);

#pragma unroll
        for (int j = 0; j < 8; j++) {
            const int cur = j & 1;
            if (j < 7) {
                const uint32_t ko = (uint32_t)(j + 1) * 16;   // k8 step = 8 halfs = 16B
                LDMATRIX_X4(fa[cur ^ 1][0], fa[cur ^ 1][1],
                            fa[cur ^ 1][2], fa[cur ^ 1][3], aBase + ko);
                LDMATRIX_X4(fb[cur ^ 1][0], fb[cur ^ 1][1],
                            fb[cur ^ 1][2], fb[cur ^ 1][3], bBase + ko);
                LDMATRIX_X4(fb[cur ^ 1][4], fb[cur ^ 1][5],
                            fb[cur ^ 1][6], fb[cur ^ 1][7],
                            bBase + 32 * RS * 2 + ko);
            }
#pragma unroll
            for (int mt = 0; mt < 2; mt++)
#pragma unroll
                for (int nt = 0; nt < 8; nt++)
                    mma_f16_k8(c[mt][nt], fa[cur][mt * 2], fa[cur][mt * 2 + 1],
                               fb[cur][nt]);
        }

        if (lane == 0) MBARRIER_ARRIVE(emptyb);

        if (i + NSTAGE < NCHUNK) {
            MBARRIER_WAIT_PARITY(emptyb, fp);
            issue_stage(i + NSTAGE);
            CP_MBAR_ARRIVE(fullb);
        }

        if (++s == NSTAGE) { s = 0; fp ^= 1; }
    }

    // ---- epilogue: out = acc / scale[f] ----
    const int row0 = bm + warp_m * 32 + (lane >> 2);
    const int col0 = bn + warp_n * 64 + (lane & 3) * 2;
#pragma unroll
    for (int nt = 0; nt < 8; nt++) {
        int col = col0 + nt * 8;
        float inv0 = 1.0f / S[col];
        float inv1 = 1.0f / S[col + 1];
#pragma unroll
        for (int mt = 0; mt < 2; mt++) {
            int r = row0 + mt * 16;
            float2 v0 = make_float2(c[mt][nt][0] * inv0, c[mt][nt][1] * inv1);
            float2 v1 = make_float2(c[mt][nt][2] * inv0, c[mt][nt][3] * inv1);
            *reinterpret_cast<float2*>(&C[(size_t)r * N_DIM + col])       = v0;
            *reinterpret_cast<float2*>(&C[(size_t)(r + 8) * N_DIM + col]) = v1;
        }
    }
}

// ---------------- launch ----------------
extern "C" void kernel_launch(void* const* d_in, const int* in_sizes, int n_in,
                              void* d_out, int out_size) {
    int ai = 0, si = 2, wi = 1;
    for (int i = 0; i < n_in; i++) {
        if (in_sizes[i] == M_DIM * K_DIM) ai = i;
        else if (in_sizes[i] == N_DIM)    si = i;
        else                              wi = i;
    }
    const float* A = (const float*)d_in[ai];
    const void*  W = d_in[wi];
    const float* S = (const float*)d_in[si];
    float*       C = (float*)d_out;

    int hint = -1;
    if (in_sizes[wi] == W_ELEMS / 2)      hint = FMT_PACKED2;
    else if (in_sizes[wi] == W_ELEMS / 8) hint = FMT_PACKED8;

    static bool attr_done = false;
    if (!attr_done) {
        cudaFuncSetAttribute(int4_gemm_kernel,
                             cudaFuncAttributeMaxDynamicSharedMemorySize, SMEM_TOTAL);
        attr_done = true;
    }

    probe_kernel<<<1, 32>>>((const uint32_t*)W, hint);
    convert_transpose_kernel<<<dim3(K_DIM / 64, N_DIM / 64), 256>>>(W);
    a_convert_kernel<<<(M_DIM * K_DIM) / 1024, 256>>>(A);

    dim3 grid(M_DIM / 128, N_DIM / 128);     // (8, 128) -- bm fastest
    int4_gemm_kernel<<<grid, 256, SMEM_TOTAL>>>(S, C);
}

// round 11
// speedup vs baseline: 1.4580x; 1.4580x over previous
#include <cuda_runtime.h>
#include <cuda_fp16.h>
#include <cuda_bf16.h>
#include <cstdint>

// IntEinsum: out[b,t,f] = sum_d x[b,t,d] * (W_int4[d,f] / scale[f])
// GEMM M=1024, K=4096, N=16384, fp32 in/out.
// Round 11: k16 MMA with two-group B ping-pong (round 10 proved the pipe
// can run ~83% occupied with interleaved LDSM/MMA; k8 doubled pipe work,
// k16 restores it). Peak fragment regs unchanged (24). Pipeline from R9.

#define M_DIM 1024
#define N_DIM 16384
#define K_DIM 4096
#define W_ELEMS (K_DIM * N_DIM)

#define BK 64
#define NCHUNK (K_DIM / BK)          // 64
#define NSTAGE 3

#define RS 72                        // smem row stride (fp16), 144B rows
#define PLANE_BYTES (128 * RS * 2)   // 18432
#define STAGE_BYTES (2 * PLANE_BYTES)// 36864: A | B_t
#define BAR_OFF     (NSTAGE * STAGE_BYTES)      // 110592
#define SMEM_TOTAL  (BAR_OFF + 64)

// ---------------- device scratch ----------------
__device__ __half g_wT[(size_t)N_DIM * K_DIM];   // weights fp16, [n][k]
__device__ __half g_a[M_DIM * K_DIM];            // activations fp16
__device__ int g_fmt;

#define FMT_I8      0
#define FMT_I32     1
#define FMT_F32     2
#define FMT_BF16    3
#define FMT_PACKED2 4
#define FMT_PACKED8 5

__device__ __forceinline__ uint32_t smem_u32(const void* p) {
    uint32_t a;
    asm("{ .reg .u64 t; cvta.to.shared.u64 t, %1; cvt.u32.u64 %0, t; }"
        : "=r"(a) : "l"(p));
    return a;
}

// ---------------- format probe (warp-parallel, proven) ----------------
__global__ void probe_kernel(const uint32_t* __restrict__ W, int hint) {
    if (hint >= 0) { if (threadIdx.x == 0) g_fmt = hint; return; }
    const int lane = threadIdx.x;
    uint32_t w0 = W[lane * 2];
    uint32_t w1 = W[lane * 2 + 1];

    bool okf = true;
#pragma unroll
    for (int j = 0; j < 2; j++) {
        float f = __uint_as_float(j ? w1 : w0);
        if (!(f >= -8.f && f <= 7.f) || f != rintf(f)) okf = false;
    }
    if (__all_sync(0xFFFFFFFFu, okf)) { if (lane == 0) g_fmt = FMT_F32; return; }

    bool okb = true;
#pragma unroll
    for (int j = 0; j < 4; j++) {
        uint16_t u = (uint16_t)((j < 2 ? w0 : w1) >> (16 * (j & 1)));
        __nv_bfloat16 b = *reinterpret_cast<__nv_bfloat16*>(&u);
        float f = __bfloat162float(b);
        if (!(f >= -8.f && f <= 7.f) || f != rintf(f)) okb = false;
    }
    if (__all_sync(0xFFFFFFFFu, okb)) { if (lane == 0) g_fmt = FMT_BF16; return; }

    bool oki = ((((int)w0) >> 4) == 0 || (((int)w0) >> 4) == -1) &&
               ((((int)w1) >> 4) == 0 || (((int)w1) >> 4) == -1);
    if (lane == 0) g_fmt = __all_sync(0xFFFFFFFFu, oki) ? FMT_I32 : FMT_I8;
}

__device__ __forceinline__ int sx_nib(uint32_t w, int shift) {
    return ((int)(w << (28 - shift))) >> 28;
}

__device__ __forceinline__ int decode_w(const void* Wv, int fmt, size_t idx) {
    if (fmt == FMT_F32)  return (int)((const float*)Wv)[idx];
    if (fmt == FMT_BF16) return (int)__bfloat162float(((const __nv_bfloat16*)Wv)[idx]);
    if (fmt == FMT_I32)  return sx_nib(((const uint32_t*)Wv)[idx], 0);
    if (fmt == FMT_I8)   return sx_nib((uint32_t)((const uint8_t*)Wv)[idx], 0);
    if (fmt == FMT_PACKED2) {
        uint32_t b = ((const uint8_t*)Wv)[idx >> 1];
        return sx_nib(b, (int)(idx & 1) * 4);
    }
    uint32_t w = ((const uint32_t*)Wv)[idx >> 3];
    return sx_nib(w, (int)(idx & 7) * 4);
}

// ---------------- W convert + transpose: [k][n] fmt -> [n][k] fp16 ----------------
__global__ void convert_transpose_kernel(const void* __restrict__ Wv) {
    __shared__ __half tile[64 * RS];
    const int fmt = g_fmt;
    const int k0 = blockIdx.x * 64;
    const int n0 = blockIdx.y * 64;
    const int tid = threadIdx.x;

#pragma unroll
    for (int it = 0; it < 16; it++) {
        int idx = tid + it * 256;
        int r = idx >> 6;                      // k-local
        int c = idx & 63;                      // n-local (coalesced reads)
        int e = decode_w(Wv, fmt, (size_t)(k0 + r) * N_DIM + (n0 + c));
        tile[c * RS + r] = __float2half((float)e);
    }
    __syncthreads();
#pragma unroll
    for (int it = 0; it < 2; it++) {
        int q = tid + it * 256;
        int n = q >> 3;
        int cg = q & 7;
        uint4 v = *reinterpret_cast<const uint4*>(&tile[n * RS + cg * 8]);
        *reinterpret_cast<uint4*>(&g_wT[(size_t)(n0 + n) * K_DIM + k0 + cg * 8]) = v;
    }
}

// ---------------- A fp32 -> fp16 ----------------
__global__ void a_convert_kernel(const float* __restrict__ A) {
    size_t i = ((size_t)blockIdx.x * blockDim.x + threadIdx.x) * 4;
    float4 v = *reinterpret_cast<const float4*>(&A[i]);
    __half2 h0 = __floats2half2_rn(v.x, v.y);
    __half2 h1 = __floats2half2_rn(v.z, v.w);
    *reinterpret_cast<uint2*>(&g_a[i]) =
        make_uint2(*(uint32_t*)&h0, *(uint32_t*)&h1);
}

// ---------------- MMA / ldmatrix / mbarrier helpers ----------------
__device__ __forceinline__ void mma_f16(float c[4], uint32_t a0, uint32_t a1,
                                        uint32_t a2, uint32_t a3,
                                        uint32_t b0, uint32_t b1) {
    asm volatile(
        "mma.sync.aligned.m16n8k16.row.col.f32.f16.f16.f32 "
        "{%0,%1,%2,%3}, {%4,%5,%6,%7}, {%8,%9}, {%0,%1,%2,%3};\n"
        : "+f"(c[0]), "+f"(c[1]), "+f"(c[2]), "+f"(c[3])
        : "r"(a0), "r"(a1), "r"(a2), "r"(a3), "r"(b0), "r"(b1));
}

#define LDMATRIX_X4(r0, r1, r2, r3, addr) \
    asm volatile("ldmatrix.sync.aligned.m8n8.x4.shared.b16 {%0,%1,%2,%3}, [%4];" \
        : "=r"(r0), "=r"(r1), "=r"(r2), "=r"(r3) : "r"(addr))

#define CP_ASYNC16(dst, src) \
    asm volatile("cp.async.cg.shared.global [%0], [%1], 16;" \
                 :: "r"(dst), "l"(src) : "memory")
#define CP_MBAR_ARRIVE(addr) \
    asm volatile("cp.async.mbarrier.arrive.noinc.shared.b64 [%0];" \
                 :: "r"(addr) : "memory")

#define MBARRIER_INIT(addr, cnt) \
    asm volatile("mbarrier.init.shared.b64 [%0], %1;" :: "r"(addr), "r"(cnt) : "memory")
#define MBARRIER_ARRIVE(addr) \
    asm volatile("mbarrier.arrive.shared.b64 _, [%0];" :: "r"(addr) : "memory")
#define MBARRIER_WAIT_PARITY(addr, ph) do {                                         \
    uint32_t _m = (addr); uint32_t _p = (ph); uint32_t _d;                          \
    asm volatile("{\n\t.reg .pred p;\n\t"                                           \
        "mbarrier.try_wait.parity.acquire.cta.shared::cta.b64 p, [%1], %2;\n\t"     \
        "selp.b32 %0, 1, 0, p;\n\t}" : "=r"(_d) : "r"(_m), "r"(_p) : "memory");     \
    if (!_d) {                                                                      \
        asm volatile("{\n\t.reg .pred P1;\n\t"                                      \
            "W%=:\n\t"                                                              \
            "mbarrier.try_wait.parity.acquire.cta.shared::cta.b64 P1, [%0], %1, 0x989680;\n\t" \
            "@P1 bra.uni D%=;\n\t"                                                  \
            "bra.uni W%=;\n\t"                                                      \
            "D%=:\n\t}" :: "r"(_m), "r"(_p) : "memory");                            \
    }                                                                               \
} while (0)

// ---------------- GEMM ----------------
__global__ __launch_bounds__(256, 2)
void int4_gemm_kernel(const float* __restrict__ S, float* __restrict__ C) {
    extern __shared__ __align__(128) char smem[];
    const uint32_t smb = smem_u32(smem);

    const int tid    = threadIdx.x;
    const int lane   = tid & 31;
    const int wid    = tid >> 5;
    const int warp_m = wid >> 1;     // 0..3 -> 32 rows
    const int warp_n = wid & 1;      // 0..1 -> 64 cols

    const int bm = blockIdx.x * 128;   // bm-fastest raster (B DRAM once)
    const int bn = blockIdx.y * 128;

    const uint32_t barb = smb + BAR_OFF;
    if (tid == 0) {
#pragma unroll
        for (int s = 0; s < NSTAGE; s++) {
            MBARRIER_INIT(barb + s * 16,     256);  // full
            MBARRIER_INIT(barb + s * 16 + 8, 8);    // empty
        }
    }
    __syncthreads();

    float c[2][8][4];
#pragma unroll
    for (int i = 0; i < 2; i++)
#pragma unroll
        for (int j = 0; j < 8; j++)
#pragma unroll
            for (int q = 0; q < 4; q++) c[i][j][q] = 0.f;

    // k16 ldmatrix lane offsets (proven in R7/R8):
    const uint32_t aOff =
        (uint32_t)(((warp_m * 32 + ((lane >> 3) & 1) * 8 + (lane & 7)) * RS
                    + ((lane >> 4) & 1) * 8) * 2);
    const uint32_t bOff =
        (uint32_t)(((warp_n * 64 + ((lane >> 4) & 1) * 8 + (lane & 7)) * RS
                    + ((lane >> 3) & 1) * 8) * 2);

    auto issue_stage = [&](int chunk) {
        const uint32_t sb = smb + (uint32_t)(chunk % NSTAGE) * STAGE_BYTES;
        const int k0 = chunk * BK;
#pragma unroll
        for (int j = 0; j < 8; j++) {
            const int buf = j >> 2;                 // 0 = A, 1 = B_t
            const int q   = (tid + j * 256) & 1023;
            const int r   = q >> 3;
            const int cg  = q & 7;
            const __half* src = (buf == 0)
                ? &g_a [(size_t)(bm + r) * K_DIM + k0 + cg * 8]
                : &g_wT[(size_t)(bn + r) * K_DIM + k0 + cg * 8];
            CP_ASYNC16(sb + buf * PLANE_BYTES + r * (RS * 2) + cg * 16, src);
        }
    };

#pragma unroll
    for (int p = 0; p < NSTAGE; p++) {
        issue_stage(p);
        CP_MBAR_ARRIVE(barb + p * 16);
    }

    uint32_t a[2][4];    // A frags, both mt           (8 regs)
    uint32_t bL[4][2];   // B frags nt0..3             (8 regs)
    uint32_t bH[4][2];   // B frags nt4..7             (8 regs)

    int s = 0, fp = 0;
    for (int i = 0; i < NCHUNK; i++) {
        const uint32_t fullb  = barb + s * 16;
        const uint32_t emptyb = fullb + 8;

        MBARRIER_WAIT_PARITY(fullb, fp);

        const uint32_t sb    = smb + (uint32_t)s * STAGE_BYTES;
        const uint32_t aBase = sb + aOff;
        const uint32_t bBase = sb + PLANE_BYTES + bOff;

        // preload kk=0: A + B-lo (nt0..3)
        LDMATRIX_X4(a[0][0], a[0][1], a[0][2], a[0][3], aBase);
        LDMATRIX_X4(a[1][0], a[1][1], a[1][2], a[1][3], aBase + 16 * RS * 2);
        LDMATRIX_X4(bL[0][0], bL[0][1], bL[1][0], bL[1][1], bBase);
        LDMATRIX_X4(bL[2][0], bL[2][1], bL[3][0], bL[3][1], bBase + 16 * RS * 2);

#pragma unroll
        for (int kk = 0; kk < 4; kk++) {
            const uint32_t ko = (uint32_t)kk * 32;          // k16 step = 32B

            // B-hi(kk): nt4..7 (p = 2,3)
            LDMATRIX_X4(bH[0][0], bH[0][1], bH[1][0], bH[1][1],
                        bBase + 2 * (16 * RS * 2) + ko);
            LDMATRIX_X4(bH[2][0], bH[2][1], bH[3][0], bH[3][1],
                        bBase + 3 * (16 * RS * 2) + ko);

            // group1: A(kk) x B-lo(kk)  (covers B-hi latency)
#pragma unroll
            for (int mt = 0; mt < 2; mt++)
#pragma unroll
                for (int nt = 0; nt < 4; nt++)
                    mma_f16(c[mt][nt], a[mt][0], a[mt][1], a[mt][2], a[mt][3],
                            bL[nt][0], bL[nt][1]);

            if (kk < 3) {   // B-lo(kk+1) into now-dead bL
                LDMATRIX_X4(bL[0][0], bL[0][1], bL[1][0], bL[1][1],
                            bBase + ko + 32);
                LDMATRIX_X4(bL[2][0], bL[2][1], bL[3][0], bL[3][1],
                            bBase + 16 * RS * 2 + ko + 32);
            }

            // group2: A(kk) x B-hi(kk)  (covers B-lo(kk+1) latency)
#pragma unroll
            for (int mt = 0; mt < 2; mt++)
#pragma unroll
                for (int nt = 0; nt < 4; nt++)
                    mma_f16(c[mt][nt + 4], a[mt][0], a[mt][1], a[mt][2], a[mt][3],
                            bH[nt][0], bH[nt][1]);

            if (kk < 3) {   // A(kk+1) into now-dead a
                LDMATRIX_X4(a[0][0], a[0][1], a[0][2], a[0][3], aBase + ko + 32);
                LDMATRIX_X4(a[1][0], a[1][1], a[1][2], a[1][3],
                            aBase + 16 * RS * 2 + ko + 32);
            }
        }

        if (lane == 0) MBARRIER_ARRIVE(emptyb);

        if (i + NSTAGE < NCHUNK) {
            MBARRIER_WAIT_PARITY(emptyb, fp);
            issue_stage(i + NSTAGE);
            CP_MBAR_ARRIVE(fullb);
        }

        if (++s == NSTAGE) { s = 0; fp ^= 1; }
    }

    // ---- epilogue: out = acc / scale[f] ----
    const int row0 = bm + warp_m * 32 + (lane >> 2);
    const int col0 = bn + warp_n * 64 + (lane & 3) * 2;
#pragma unroll
    for (int nt = 0; nt < 8; nt++) {
        int col = col0 + nt * 8;
        float inv0 = 1.0f / S[col];
        float inv1 = 1.0f / S[col + 1];
#pragma unroll
        for (int mt = 0; mt < 2; mt++) {
            int r = row0 + mt * 16;
            float2 v0 = make_float2(c[mt][nt][0] * inv0, c[mt][nt][1] * inv1);
            float2 v1 = make_float2(c[mt][nt][2] * inv0, c[mt][nt][3] * inv1);
            *reinterpret_cast<float2*>(&C[(size_t)r * N_DIM + col])       = v0;
            *reinterpret_cast<float2*>(&C[(size_t)(r + 8) * N_DIM + col]) = v1;
        }
    }
}

// ---------------- launch ----------------
extern "C" void kernel_launch(void* const* d_in, const int* in_sizes, int n_in,
                              void* d_out, int out_size) {
    int ai = 0, si = 2, wi = 1;
    for (int i = 0; i < n_in; i++) {
        if (in_sizes[i] == M_DIM * K_DIM) ai = i;
        else if (in_sizes[i] == N_DIM)    si = i;
        else                              wi = i;
    }
    const float* A = (const float*)d_in[ai];
    const void*  W = d_in[wi];
    const float* S = (const float*)d_in[si];
    float*       C = (float*)d_out;

    int hint = -1;
    if (in_sizes[wi] == W_ELEMS / 2)      hint = FMT_PACKED2;
    else if (in_sizes[wi] == W_ELEMS / 8) hint = FMT_PACKED8;

    static bool attr_done = false;
    if (!attr_done) {
        cudaFuncSetAttribute(int4_gemm_kernel,
                             cudaFuncAttributeMaxDynamicSharedMemorySize, SMEM_TOTAL);
        attr_done = true;
    }

    probe_kernel<<<1, 32>>>((const uint32_t*)W, hint);
    convert_transpose_kernel<<<dim3(K_DIM / 64, N_DIM / 64), 256>>>(W);
    a_convert_kernel<<<(M_DIM * K_DIM) / 1024, 256>>>(A);

    dim3 grid(M_DIM / 128, N_DIM / 128);     // (8, 128) -- bm fastest
    int4_gemm_kernel<<<grid, 256, SMEM_TOTAL>>>(S, C);
}

// round 12
// speedup vs baseline: 1.4946x; 1.0251x over previous
#include <cuda_runtime.h>
#include <cuda_fp16.h>
#include <cuda_bf16.h>
#include <cstdint>

// IntEinsum: out[b,t,f] = sum_d x[b,t,d] * (W_int4[d,f] / scale[f])
// GEMM M=1024, K=4096, N=16384, fp32 in/out.
// Round 12: B staged as packed-permuted int8 (halves B smem traffic, the
// measured bottleneck), expanded to fp16 in registers via PRMT+SUB.f16x2
// (exact for int4). A stays fp16. Pipeline/raster/epilogue frozen from R9.

#define M_DIM 1024
#define N_DIM 16384
#define K_DIM 4096
#define W_ELEMS (K_DIM * N_DIM)

#define BK 64
#define NCHUNK (K_DIM / BK)          // 64
#define NSTAGE 3

#define RS 72                        // A smem row stride (fp16), 144B rows
#define A_PLANE (128 * RS * 2)       // 18432
#define B_RS 80                      // B smem row stride (int8 bytes)
#define B_PLANE (128 * B_RS)         // 10240
#define STAGE_BYTES (A_PLANE + B_PLANE)          // 28672
#define BAR_OFF     (NSTAGE * STAGE_BYTES)       // 86016
#define SMEM_TOTAL  (BAR_OFF + 64)

// ---------------- device scratch ----------------
__device__ uint8_t g_w8p[(size_t)N_DIM * K_DIM]; // packed biased permuted int4
__device__ __half  g_a[M_DIM * K_DIM];           // activations fp16
__device__ int g_fmt;

#define FMT_I8      0
#define FMT_I32     1
#define FMT_F32     2
#define FMT_BF16    3
#define FMT_PACKED2 4
#define FMT_PACKED8 5

__device__ __forceinline__ uint32_t smem_u32(const void* p) {
    uint32_t a;
    asm("{ .reg .u64 t; cvta.to.shared.u64 t, %1; cvt.u32.u64 %0, t; }"
        : "=r"(a) : "l"(p));
    return a;
}

// ---------------- format probe (warp-parallel, proven) ----------------
__global__ void probe_kernel(const uint32_t* __restrict__ W, int hint) {
    if (hint >= 0) { if (threadIdx.x == 0) g_fmt = hint; return; }
    const int lane = threadIdx.x;
    uint32_t w0 = W[lane * 2];
    uint32_t w1 = W[lane * 2 + 1];

    bool okf = true;
#pragma unroll
    for (int j = 0; j < 2; j++) {
        float f = __uint_as_float(j ? w1 : w0);
        if (!(f >= -8.f && f <= 7.f) || f != rintf(f)) okf = false;
    }
    if (__all_sync(0xFFFFFFFFu, okf)) { if (lane == 0) g_fmt = FMT_F32; return; }

    bool okb = true;
#pragma unroll
    for (int j = 0; j < 4; j++) {
        uint16_t u = (uint16_t)((j < 2 ? w0 : w1) >> (16 * (j & 1)));
        __nv_bfloat16 b = *reinterpret_cast<__nv_bfloat16*>(&u);
        float f = __bfloat162float(b);
        if (!(f >= -8.f && f <= 7.f) || f != rintf(f)) okb = false;
    }
    if (__all_sync(0xFFFFFFFFu, okb)) { if (lane == 0) g_fmt = FMT_BF16; return; }

    bool oki = ((((int)w0) >> 4) == 0 || (((int)w0) >> 4) == -1) &&
               ((((int)w1) >> 4) == 0 || (((int)w1) >> 4) == -1);
    if (lane == 0) g_fmt = __all_sync(0xFFFFFFFFu, oki) ? FMT_I32 : FMT_I8;
}

__device__ __forceinline__ int sx_nib(uint32_t w, int shift) {
    return ((int)(w << (28 - shift))) >> 28;
}

__device__ __forceinline__ int decode_w(const void* Wv, int fmt, size_t idx) {
    if (fmt == FMT_F32)  return (int)((const float*)Wv)[idx];
    if (fmt == FMT_BF16) return (int)__bfloat162float(((const __nv_bfloat16*)Wv)[idx]);
    if (fmt == FMT_I32)  return sx_nib(((const uint32_t*)Wv)[idx], 0);
    if (fmt == FMT_I8)   return sx_nib((uint32_t)((const uint8_t*)Wv)[idx], 0);
    if (fmt == FMT_PACKED2) {
        uint32_t b = ((const uint8_t*)Wv)[idx >> 1];
        return sx_nib(b, (int)(idx & 1) * 4);
    }
    uint32_t w = ((const uint32_t*)Wv)[idx >> 3];
    return sx_nib(w, (int)(idx & 7) * 4);
}

// ---------------- W convert+pack: [k][n] fmt -> [n][k] biased permuted u8 ----
// Per thread: one n, 32 consecutive k. Byte order per k16 block:
// out[4q+{0,1,2,3}] = in[{2q, 2q+1, 2q+8, 2q+9}]  (q = 0..3)
__global__ void convert_pack_kernel(const void* __restrict__ Wv) {
    const int fmt = g_fmt;
    const int lane = threadIdx.x & 31;
    const int gw = (blockIdx.x * blockDim.x + threadIdx.x) >> 5;
    const int n  = (gw & 511) * 32 + lane;   // 512 n-warps x 32 lanes = 16384
    const int k0 = (gw >> 9) * 32;           // 128 k-blocks of 32

#pragma unroll
    for (int g = 0; g < 2; g++) {
        uint32_t u[16];
#pragma unroll
        for (int j = 0; j < 16; j++)
            u[j] = (uint32_t)(decode_w(Wv, fmt,
                       (size_t)(k0 + g * 16 + j) * N_DIM + n) + 8) & 0xFF;
        uint4 o;
        o.x = u[0] | (u[1] << 8) | (u[8]  << 16) | (u[9]  << 24);
        o.y = u[2] | (u[3] << 8) | (u[10] << 16) | (u[11] << 24);
        o.z = u[4] | (u[5] << 8) | (u[12] << 16) | (u[13] << 24);
        o.w = u[6] | (u[7] << 8) | (u[14] << 16) | (u[15] << 24);
        *reinterpret_cast<uint4*>(&g_w8p[(size_t)n * K_DIM + k0 + g * 16]) = o;
    }
}

// ---------------- A fp32 -> fp16 ----------------
__global__ void a_convert_kernel(const float* __restrict__ A) {
    size_t i = ((size_t)blockIdx.x * blockDim.x + threadIdx.x) * 4;
    float4 v = *reinterpret_cast<const float4*>(&A[i]);
    __half2 h0 = __floats2half2_rn(v.x, v.y);
    __half2 h1 = __floats2half2_rn(v.z, v.w);
    *reinterpret_cast<uint2*>(&g_a[i]) =
        make_uint2(*(uint32_t*)&h0, *(uint32_t*)&h1);
}

// ---------------- MMA / ldmatrix / mbarrier helpers ----------------
__device__ __forceinline__ void mma_f16(float c[4], uint32_t a0, uint32_t a1,
                                        uint32_t a2, uint32_t a3,
                                        uint32_t b0, uint32_t b1) {
    asm volatile(
        "mma.sync.aligned.m16n8k16.row.col.f32.f16.f16.f32 "
        "{%0,%1,%2,%3}, {%4,%5,%6,%7}, {%8,%9}, {%0,%1,%2,%3};\n"
        : "+f"(c[0]), "+f"(c[1]), "+f"(c[2]), "+f"(c[3])
        : "r"(a0), "r"(a1), "r"(a2), "r"(a3), "r"(b0), "r"(b1));
}

// expand packed biased int4x4 -> two fp16x2 regs (exact): 1024+u via 0x64
// exponent splice, then subtract 1032.
__device__ __forceinline__ void expand_b(uint32_t pk, uint32_t& lo, uint32_t& hi) {
    uint32_t l, h;
    asm("prmt.b32 %0, %2, %3, 0x4140;\n\t"
        "prmt.b32 %1, %2, %3, 0x4342;"
        : "=r"(l), "=r"(h) : "r"(pk), "r"(0x64646464u));
    asm("sub.f16x2 %0, %1, %2;" : "=r"(lo) : "r"(l), "r"(0x64086408u));
    asm("sub.f16x2 %0, %1, %2;" : "=r"(hi) : "r"(h), "r"(0x64086408u));
}

#define LDMATRIX_X4(r0, r1, r2, r3, addr) \
    asm volatile("ldmatrix.sync.aligned.m8n8.x4.shared.b16 {%0,%1,%2,%3}, [%4];" \
        : "=r"(r0), "=r"(r1), "=r"(r2), "=r"(r3) : "r"(addr))

#define CP_ASYNC16(dst, src) \
    asm volatile("cp.async.cg.shared.global [%0], [%1], 16;" \
                 :: "r"(dst), "l"(src) : "memory")
#define CP_MBAR_ARRIVE(addr) \
    asm volatile("cp.async.mbarrier.arrive.noinc.shared.b64 [%0];" \
                 :: "r"(addr) : "memory")

#define MBARRIER_INIT(addr, cnt) \
    asm volatile("mbarrier.init.shared.b64 [%0], %1;" :: "r"(addr), "r"(cnt) : "memory")
#define MBARRIER_ARRIVE(addr) \
    asm volatile("mbarrier.arrive.shared.b64 _, [%0];" :: "r"(addr) : "memory")
#define MBARRIER_WAIT_PARITY(addr, ph) do {                                         \
    uint32_t _m = (addr); uint32_t _p = (ph); uint32_t _d;                          \
    asm volatile("{\n\t.reg .pred p;\n\t"                                           \
        "mbarrier.try_wait.parity.acquire.cta.shared::cta.b64 p, [%1], %2;\n\t"     \
        "selp.b32 %0, 1, 0, p;\n\t}" : "=r"(_d) : "r"(_m), "r"(_p) : "memory");     \
    if (!_d) {                                                                      \
        asm volatile("{\n\t.reg .pred P1;\n\t"                                      \
            "W%=:\n\t"                                                              \
            "mbarrier.try_wait.parity.acquire.cta.shared::cta.b64 P1, [%0], %1, 0x989680;\n\t" \
            "@P1 bra.uni D%=;\n\t"                                                  \
            "bra.uni W%=;\n\t"                                                      \
            "D%=:\n\t}" :: "r"(_m), "r"(_p) : "memory");                            \
    }                                                                               \
} while (0)

// ---------------- GEMM ----------------
__global__ __launch_bounds__(256, 2)
void int4_gemm_kernel(const float* __restrict__ S, float* __restrict__ C) {
    extern __shared__ __align__(128) char smem[];
    const uint32_t smb = smem_u32(smem);

    const int tid    = threadIdx.x;
    const int lane   = tid & 31;
    const int wid    = tid >> 5;
    const int warp_m = wid >> 1;     // 0..3 -> 32 rows
    const int warp_n = wid & 1;      // 0..1 -> 64 cols

    const int bm = blockIdx.x * 128;   // bm-fastest raster (B DRAM once)
    const int bn = blockIdx.y * 128;

    const uint32_t barb = smb + BAR_OFF;
    if (tid == 0) {
#pragma unroll
        for (int s = 0; s < NSTAGE; s++) {
            MBARRIER_INIT(barb + s * 16,     256);  // full
            MBARRIER_INIT(barb + s * 16 + 8, 8);    // empty
        }
    }
    __syncthreads();

    float c[2][8][4];
#pragma unroll
    for (int i = 0; i < 2; i++)
#pragma unroll
        for (int j = 0; j < 8; j++)
#pragma unroll
            for (int q = 0; q < 4; q++) c[i][j][q] = 0.f;

    // A k16 ldmatrix lane offset (proven R7/R8)
    const uint32_t aOff =
        (uint32_t)(((warp_m * 32 + ((lane >> 3) & 1) * 8 + (lane & 7)) * RS
                    + ((lane >> 4) & 1) * 8) * 2);
    // B packed int8: x4 mats = n-groups {0,8,16,24} -> row = warp_n*64 + lane
    const uint32_t bOff = (uint32_t)((warp_n * 64 + lane) * B_RS);

    auto issue_stage = [&](int chunk) {
        const uint32_t sb = smb + (uint32_t)(chunk % NSTAGE) * STAGE_BYTES;
        const int k0 = chunk * BK;
        // A: 1024 x 16B
#pragma unroll
        for (int j = 0; j < 4; j++) {
            const int q  = (tid + j * 256) & 1023;
            const int r  = q >> 3;
            const int cg = q & 7;
            CP_ASYNC16(sb + r * (RS * 2) + cg * 16,
                       &g_a[(size_t)(bm + r) * K_DIM + k0 + cg * 8]);
        }
        // B packed: 512 x 16B (128 rows x 64B)
#pragma unroll
        for (int j = 0; j < 2; j++) {
            const int q  = (tid + j * 256) & 511;
            const int r  = q >> 2;
            const int cg = q & 3;
            CP_ASYNC16(sb + A_PLANE + r * B_RS + cg * 16,
                       &g_w8p[(size_t)(bn + r) * K_DIM + k0 + cg * 16]);
        }
    };

#pragma unroll
    for (int p = 0; p < NSTAGE; p++) {
        issue_stage(p);
        CP_MBAR_ARRIVE(barb + p * 16);
    }

    int s = 0, fp = 0;
    for (int i = 0; i < NCHUNK; i++) {
        const uint32_t fullb  = barb + s * 16;
        const uint32_t emptyb = fullb + 8;

        MBARRIER_WAIT_PARITY(fullb, fp);

        const uint32_t sb    = smb + (uint32_t)s * STAGE_BYTES;
        const uint32_t aBase = sb + aOff;
        const uint32_t bBase = sb + A_PLANE + bOff;

#pragma unroll
        for (int kk = 0; kk < 4; kk++) {
            uint32_t a[2][4];
            LDMATRIX_X4(a[0][0], a[0][1], a[0][2], a[0][3], aBase + kk * 32);
            LDMATRIX_X4(a[1][0], a[1][1], a[1][2], a[1][3],
                        aBase + 16 * RS * 2 + kk * 32);

            uint32_t pk[8];
            LDMATRIX_X4(pk[0], pk[1], pk[2], pk[3], bBase + kk * 16);
            LDMATRIX_X4(pk[4], pk[5], pk[6], pk[7],
                        bBase + 32 * B_RS + kk * 16);

            uint32_t be[4][2];
            // expand + MMA nt0-3
#pragma unroll
            for (int nt = 0; nt < 4; nt++) expand_b(pk[nt], be[nt][0], be[nt][1]);
#pragma unroll
            for (int mt = 0; mt < 2; mt++)
#pragma unroll
                for (int nt = 0; nt < 4; nt++)
                    mma_f16(c[mt][nt], a[mt][0], a[mt][1], a[mt][2], a[mt][3],
                            be[nt][0], be[nt][1]);
            // expand + MMA nt4-7
#pragma unroll
            for (int nt = 0; nt < 4; nt++) expand_b(pk[nt + 4], be[nt][0], be[nt][1]);
#pragma unroll
            for (int mt = 0; mt < 2; mt++)
#pragma unroll
                for (int nt = 0; nt < 4; nt++)
                    mma_f16(c[mt][nt + 4], a[mt][0], a[mt][1], a[mt][2], a[mt][3],
                            be[nt][0], be[nt][1]);
        }

        if (lane == 0) MBARRIER_ARRIVE(emptyb);

        if (i + NSTAGE < NCHUNK) {
            MBARRIER_WAIT_PARITY(emptyb, fp);
            issue_stage(i + NSTAGE);
            CP_MBAR_ARRIVE(fullb);
        }

        if (++s == NSTAGE) { s = 0; fp ^= 1; }
    }

    // ---- epilogue: out = acc / scale[f] ----
    const int row0 = bm + warp_m * 32 + (lane >> 2);
    const int col0 = bn + warp_n * 64 + (lane & 3) * 2;
#pragma unroll
    for (int nt = 0; nt < 8; nt++) {
        int col = col0 + nt * 8;
        float inv0 = 1.0f / S[col];
        float inv1 = 1.0f / S[col + 1];
#pragma unroll
        for (int mt = 0; mt < 2; mt++) {
            int r = row0 + mt * 16;
            float2 v0 = make_float2(c[mt][nt][0] * inv0, c[mt][nt][1] * inv1);
            float2 v1 = make_float2(c[mt][nt][2] * inv0, c[mt][nt][3] * inv1);
            *reinterpret_cast<float2*>(&C[(size_t)r * N_DIM + col])       = v0;
            *reinterpret_cast<float2*>(&C[(size_t)(r + 8) * N_DIM + col]) = v1;
        }
    }
}

// ---------------- launch ----------------
extern "C" void kernel_launch(void* const* d_in, const int* in_sizes, int n_in,
                              void* d_out, int out_size) {
    int ai = 0, si = 2, wi = 1;
    for (int i = 0; i < n_in; i++) {
        if (in_sizes[i] == M_DIM * K_DIM) ai = i;
        else if (in_sizes[i] == N_DIM)    si = i;
        else                              wi = i;
    }
    const float* A = (const float*)d_in[ai];
    const void*  W = d_in[wi];
    const float* S = (const float*)d_in[si];
    float*       C = (float*)d_out;

    int hint = -1;
    if (in_sizes[wi] == W_ELEMS / 2)      hint = FMT_PACKED2;
    else if (in_sizes[wi] == W_ELEMS / 8) hint = FMT_PACKED8;

    static bool attr_done = false;
    if (!attr_done) {
        cudaFuncSetAttribute(int4_gemm_kernel,
                             cudaFuncAttributeMaxDynamicSharedMemorySize, SMEM_TOTAL);
        attr_done = true;
    }

    probe_kernel<<<1, 32>>>((const uint32_t*)W, hint);
    convert_pack_kernel<<<(N_DIM / 32) * (K_DIM / 32) / 8, 256>>>(W);
    a_convert_kernel<<<(M_DIM * K_DIM) / 1024, 256>>>(A);

    dim3 grid(M_DIM / 128, N_DIM / 128);     // (8, 128) -- bm fastest
    int4_gemm_kernel<<<grid, 256, SMEM_TOTAL>>>(S, C);
}